// round 6
// baseline (speedup 1.0000x reference)
#include <cuda_runtime.h>
#include <cuda_bf16.h>
#include <math.h>
#include <stdint.h>

// Problem dims (fixed by the dataset)
#define NN 8192
#define DD 1024
#define HH 4096
#define KK 4096   // codebook

// ---------------- scratch (static __device__, allocation-free) ----------------
__device__ float g_hcat[(size_t)NN * 2 * HH];   // [8192, 8192]
__device__ float g_h2[(size_t)NN * HH];         // [8192, 4096] (reused for scores)
__device__ float g_h3[(size_t)NN * HH];         // [8192, 4096]
__device__ float g_z[(size_t)NN * DD];          // [8192, 1024]
__device__ float g_e2[KK];
__device__ int   g_idx[NN];

// ---------------- packed f32x2 FMA ----------------
__device__ __forceinline__ void fma2(unsigned long long& c,
                                     unsigned long long a,
                                     unsigned long long b) {
    asm("fma.rn.f32x2 %0, %1, %2, %0;" : "+l"(c) : "l"(a), "l"(b));
}
__device__ __forceinline__ float lo_f(unsigned long long v) {
    return __uint_as_float((unsigned)(v & 0xFFFFFFFFull));
}
__device__ __forceinline__ float hi_f(unsigned long long v) {
    return __uint_as_float((unsigned)(v >> 32));
}

// ============================ FFMA2 GEMM ======================================
// C[m,n] = act( sum_k A[m,k]*B[n,k] + bias[n] ),  A:[M,K], B:[N,K] row-major.
// 128x128 tile, BK=16, 256 threads, 8x8 per thread as 8 rows x 4 f32x2 pairs.
// A duplicated in smem ((a,a) pairs) so LDS.64 yields broadcast pairs directly.
// k-accumulation order per output element identical to the round-1 kernel.
#define BM 128
#define BN 128
#define BK 16

// ACT: 0=bias  1=fourier(bias+acc)  2=cat raw+fourier (ldc=2N)  3=score bias-2*acc
template <int ACT>
__global__ __launch_bounds__(256, 2)
void gemm_f2(const float* __restrict__ A, const float* __restrict__ B,
             const float* __restrict__ bias, float* __restrict__ C,
             int M, int N, int K, int ldc)
{
    __shared__ float As2[2][BK][2 * BM];   // duplicated pairs: 2*16KB
    __shared__ float Bs[2][BK][BN];        // 2*8KB   (total 48KB)

    const int tid = threadIdx.x;
    const int tx = tid & 15;            // 16 col-pair groups
    const int ty = tid >> 4;            // 16 row groups
    const int m0 = blockIdx.y * BM;
    const int n0 = blockIdx.x * BN;

    // loader mapping: thread t -> row lr = t>>1, k-half lk = (t&1)*8
    const int lr = tid >> 1;
    const int lk = (tid & 1) * 8;
    const float* ag = A + (size_t)(m0 + lr) * K + lk;
    const float* bg = B + (size_t)(n0 + lr) * K + lk;

    const int nk = K / BK;

    float4 av0, av1, bv0, bv1;
    av0 = *(const float4*)(ag);     av1 = *(const float4*)(ag + 4);
    bv0 = *(const float4*)(bg);     bv1 = *(const float4*)(bg + 4);

    // store chunk 0 into stage 0
    {
        const int m2 = 2 * lr;
        *(float2*)&As2[0][lk + 0][m2] = make_float2(av0.x, av0.x);
        *(float2*)&As2[0][lk + 1][m2] = make_float2(av0.y, av0.y);
        *(float2*)&As2[0][lk + 2][m2] = make_float2(av0.z, av0.z);
        *(float2*)&As2[0][lk + 3][m2] = make_float2(av0.w, av0.w);
        *(float2*)&As2[0][lk + 4][m2] = make_float2(av1.x, av1.x);
        *(float2*)&As2[0][lk + 5][m2] = make_float2(av1.y, av1.y);
        *(float2*)&As2[0][lk + 6][m2] = make_float2(av1.z, av1.z);
        *(float2*)&As2[0][lk + 7][m2] = make_float2(av1.w, av1.w);
        Bs[0][lk + 0][lr] = bv0.x;  Bs[0][lk + 1][lr] = bv0.y;
        Bs[0][lk + 2][lr] = bv0.z;  Bs[0][lk + 3][lr] = bv0.w;
        Bs[0][lk + 4][lr] = bv1.x;  Bs[0][lk + 5][lr] = bv1.y;
        Bs[0][lk + 6][lr] = bv1.z;  Bs[0][lk + 7][lr] = bv1.w;
    }
    __syncthreads();

    unsigned long long acc2[8][4];
#pragma unroll
    for (int i = 0; i < 8; i++)
#pragma unroll
        for (int j = 0; j < 4; j++) acc2[i][j] = 0ull;

    for (int c = 0; c < nk; c++) {
        // prefetch next chunk into registers (overlaps with compute below)
        if (c + 1 < nk) {
            const float* a = ag + (size_t)(c + 1) * BK;
            const float* b = bg + (size_t)(c + 1) * BK;
            av0 = *(const float4*)(a);     av1 = *(const float4*)(a + 4);
            bv0 = *(const float4*)(b);     bv1 = *(const float4*)(b + 4);
        }

        const float (*as)[2 * BM] = As2[c & 1];
        const float (*bs)[BN]     = Bs[c & 1];

#pragma unroll
        for (int kk = 0; kk < BK; kk++) {
            unsigned long long A2[8], B2[4];
#pragma unroll
            for (int i = 0; i < 8; i++)
                A2[i] = *(const unsigned long long*)&as[kk][2 * ty + 32 * i];
#pragma unroll
            for (int j = 0; j < 4; j++)
                B2[j] = *(const unsigned long long*)&bs[kk][2 * tx + 32 * j];
#pragma unroll
            for (int i = 0; i < 8; i++)
#pragma unroll
                for (int j = 0; j < 4; j++)
                    fma2(acc2[i][j], A2[i], B2[j]);
        }

        // store next chunk into the other stage
        if (c + 1 < nk) {
            const int s = (c + 1) & 1;
            const int m2 = 2 * lr;
            *(float2*)&As2[s][lk + 0][m2] = make_float2(av0.x, av0.x);
            *(float2*)&As2[s][lk + 1][m2] = make_float2(av0.y, av0.y);
            *(float2*)&As2[s][lk + 2][m2] = make_float2(av0.z, av0.z);
            *(float2*)&As2[s][lk + 3][m2] = make_float2(av0.w, av0.w);
            *(float2*)&As2[s][lk + 4][m2] = make_float2(av1.x, av1.x);
            *(float2*)&As2[s][lk + 5][m2] = make_float2(av1.y, av1.y);
            *(float2*)&As2[s][lk + 6][m2] = make_float2(av1.z, av1.z);
            *(float2*)&As2[s][lk + 7][m2] = make_float2(av1.w, av1.w);
            Bs[s][lk + 0][lr] = bv0.x;  Bs[s][lk + 1][lr] = bv0.y;
            Bs[s][lk + 2][lr] = bv0.z;  Bs[s][lk + 3][lr] = bv0.w;
            Bs[s][lk + 4][lr] = bv1.x;  Bs[s][lk + 5][lr] = bv1.y;
            Bs[s][lk + 6][lr] = bv1.z;  Bs[s][lk + 7][lr] = bv1.w;
        }
        __syncthreads();
    }

    // ---- epilogue ----
#pragma unroll
    for (int i = 0; i < 8; i++) {
        const int m = m0 + ty + 16 * i;
        float* crow = C + (size_t)m * ldc;
#pragma unroll
        for (int j = 0; j < 4; j++) {
            const int n = n0 + 2 * tx + 32 * j;   // even column
            float s0 = lo_f(acc2[i][j]);
            float s1 = hi_f(acc2[i][j]);
            if (ACT == 0) {
                crow[n]     = s0 + bias[n];
                crow[n + 1] = s1 + bias[n + 1];
            } else if (ACT == 1) {
                float v0 = s0 + bias[n];
                float v1 = s1 + bias[n + 1];
                crow[n]     = sinf(v0);   // even col -> sin
                crow[n + 1] = cosf(v1);   // odd col  -> cos
            } else if (ACT == 2) {
                float v0 = s0 + bias[n];
                float v1 = s1 + bias[n + 1];
                crow[n]         = v0;
                crow[n + 1]     = v1;
                crow[N + n]     = sinf(v0);
                crow[N + n + 1] = cosf(v1);
            } else {  // 3: score = e2[n] - 2*acc
                crow[n]     = bias[n]     - 2.0f * s0;
                crow[n + 1] = bias[n + 1] - 2.0f * s1;
            }
        }
    }
}

// ---------------- e2[k] = ||emb[k]||^2 ----------------
__global__ void e2_kernel(const float* __restrict__ emb, float* __restrict__ e2)
{
    __shared__ float red[256];
    const int k = blockIdx.x;
    const float* row = emb + (size_t)k * DD;
    float s = 0.f;
    for (int d = threadIdx.x; d < DD; d += 256) { float v = row[d]; s += v * v; }
    red[threadIdx.x] = s;
    __syncthreads();
    for (int o = 128; o > 0; o >>= 1) {
        if (threadIdx.x < o) red[threadIdx.x] += red[threadIdx.x + o];
        __syncthreads();
    }
    if (threadIdx.x == 0) e2[k] = red[0];
}

// ---------------- per-row argmin over K scores (first-index tie-break) -------
__global__ void argmin_kernel(const float* __restrict__ scores, int* __restrict__ idx)
{
    __shared__ float bv[256];
    __shared__ int   bi[256];
    const int n = blockIdx.x;
    const float* row = scores + (size_t)n * KK;
    float best = 3.4e38f;
    int besti = 0;
    for (int k = threadIdx.x; k < KK; k += 256) {
        float v = row[k];
        if (v < best) { best = v; besti = k; }
    }
    bv[threadIdx.x] = best;
    bi[threadIdx.x] = besti;
    __syncthreads();
    for (int o = 128; o > 0; o >>= 1) {
        if (threadIdx.x < o) {
            float vo = bv[threadIdx.x + o];
            int   io = bi[threadIdx.x + o];
            if (vo < bv[threadIdx.x] ||
                (vo == bv[threadIdx.x] && io < bi[threadIdx.x])) {
                bv[threadIdx.x] = vo; bi[threadIdx.x] = io;
            }
        }
        __syncthreads();
    }
    if (threadIdx.x == 0) idx[n] = bi[0];
}

// ---------------- mueller hash (numpy int64 wraparound semantics) ------------
__device__ __forceinline__ long long mueller_hash(long long x)
{
    const unsigned long long C = 73244475ull;
    x = (long long)((unsigned long long)((x >> 16) ^ x) * C);
    x = (long long)((unsigned long long)((x >> 16) ^ x) * C);
    return (x >> 16) ^ x;
}

// ---------------- quantize: out[n] = sum_{i=1..3} emb[hash(idx+i*K)&(K-1)]/3 --
__global__ void quant_kernel(const float* __restrict__ emb,
                             const int* __restrict__ idx,
                             float* __restrict__ out)
{
    const int n = blockIdx.x;
    const long long id = (long long)idx[n];
    int s0 = (int)(mueller_hash(id + 1LL * KK) & (long long)(KK - 1));
    int s1 = (int)(mueller_hash(id + 2LL * KK) & (long long)(KK - 1));
    int s2 = (int)(mueller_hash(id + 3LL * KK) & (long long)(KK - 1));
    const float4* e0 = (const float4*)(emb + (size_t)s0 * DD);
    const float4* e1 = (const float4*)(emb + (size_t)s1 * DD);
    const float4* e2p = (const float4*)(emb + (size_t)s2 * DD);
    float4* o = (float4*)(out + (size_t)n * DD);
    const int d = threadIdx.x;
    float4 a = e0[d], b = e1[d], c = e2p[d];
    float4 r;
    r.x = (a.x / 3.0f + b.x / 3.0f) + c.x / 3.0f;
    r.y = (a.y / 3.0f + b.y / 3.0f) + c.y / 3.0f;
    r.z = (a.z / 3.0f + b.z / 3.0f) + c.z / 3.0f;
    r.w = (a.w / 3.0f + b.w / 3.0f) + c.w / 3.0f;
    o[d] = r;
}

// ---------------- host launcher ----------------
extern "C" void kernel_launch(void* const* d_in, const int* in_sizes, int n_in,
                              void* d_out, int out_size)
{
    const float* x   = (const float*)d_in[0];
    const float* w1  = (const float*)d_in[1];
    const float* b1  = (const float*)d_in[2];
    const float* w2  = (const float*)d_in[3];
    const float* b2  = (const float*)d_in[4];
    const float* w3  = (const float*)d_in[5];
    const float* b3  = (const float*)d_in[6];
    const float* w4  = (const float*)d_in[7];
    const float* b4  = (const float*)d_in[8];
    const float* emb = (const float*)d_in[9];
    float* out = (float*)d_out;

    float *hcat, *h2, *h3, *z, *e2d;
    int* idx;
    cudaGetSymbolAddress((void**)&hcat, g_hcat);
    cudaGetSymbolAddress((void**)&h2,   g_h2);
    cudaGetSymbolAddress((void**)&h3,   g_h3);
    cudaGetSymbolAddress((void**)&z,    g_z);
    cudaGetSymbolAddress((void**)&e2d,  g_e2);
    cudaGetSymbolAddress((void**)&idx,  g_idx);

    e2_kernel<<<KK, 256>>>(emb, e2d);

    // G1: hcat = [h1, fourier(h1)], h1 = x @ w1.T + b1
    gemm_f2<2><<<dim3(HH / BN, NN / BM), 256>>>(x, w1, b1, hcat, NN, HH, DD, 2 * HH);
    // G2: h2 = fourier(hcat @ w2.T + b2)
    gemm_f2<1><<<dim3(HH / BN, NN / BM), 256>>>(hcat, w2, b2, h2, NN, HH, 2 * HH, HH);
    // G3: h3 = fourier(h2 @ w3.T + b3)
    gemm_f2<1><<<dim3(HH / BN, NN / BM), 256>>>(h2, w3, b3, h3, NN, HH, HH, HH);
    // G4: z = h3 @ w4.T + b4
    gemm_f2<0><<<dim3(DD / BN, NN / BM), 256>>>(h3, w4, b4, z, NN, DD, HH, DD);
    // G5: scores = e2[k] - 2 * z @ emb.T  (reuse h2)
    gemm_f2<3><<<dim3(KK / BN, NN / BM), 256>>>(z, emb, e2d, h2, NN, KK, DD, KK);

    argmin_kernel<<<NN, 256>>>(h2, idx);
    quant_kernel<<<NN, 256>>>(emb, idx, out);
}

// round 7
// speedup vs baseline: 1.0290x; 1.0290x over previous
#include <cuda_runtime.h>
#include <cuda_bf16.h>
#include <math.h>
#include <stdint.h>

// Problem dims (fixed by the dataset)
#define NN 8192
#define DD 1024
#define HH 4096
#define KK 4096   // codebook

// ---------------- scratch (static __device__, allocation-free) ----------------
__device__ float g_hcat[(size_t)NN * 2 * HH];   // [8192, 8192]
__device__ float g_h2[(size_t)NN * HH];         // [8192, 4096] (reused for scores)
__device__ float g_h3[(size_t)NN * HH];         // [8192, 4096]
__device__ float g_z[(size_t)NN * DD];          // [8192, 1024]
__device__ float g_e2[KK];
__device__ int   g_idx[NN];

// ============================ FFMA GEMM (pipelined) ===========================
// C[m,n] = act( sum_k A[m,k]*B[n,k] + bias[n] ),  A:[M,K], B:[N,K] row-major.
// 128x128 tile, BK=16, 256 threads, 8x8 per thread, LDS.128 fragments.
// Per-element accumulation: single acc, strict ascending k via fmaf ->
// bit-identical to the round-1 kernel (which passed with rel_err 6.29e-8).
// Pipeline: one barrier per chunk; LDG for chunk c+2 issued while computing
// chunk c (register-staged), STS of chunk c+1 at iteration start.
#define BM 128
#define BN 128
#define BK 16
#define TM 8
#define TN 8

// ACT: 0=bias  1=fourier(bias+acc)  2=cat raw+fourier (ldc=2N)  3=score bias-2*acc
template <int ACT>
__global__ __launch_bounds__(256, 2)
void gemm_ff(const float* __restrict__ A, const float* __restrict__ B,
             const float* __restrict__ bias, float* __restrict__ C,
             int M, int N, int K, int ldc)
{
    __shared__ float As[2][BK][BM];   // 16 KB
    __shared__ float Bs[2][BK][BN];   // 16 KB

    const int tid = threadIdx.x;
    const int tx = tid & 15;            // 16 col groups of 8
    const int ty = tid >> 4;            // 16 row groups of 8
    const int m0 = blockIdx.y * BM;
    const int n0 = blockIdx.x * BN;

    // loader mapping: 2 threads per row, 8 k's (2 float4) each
    const int lr = tid >> 1;            // row 0..127
    const int lk = (tid & 1) * 8;       // k offset 0 or 8
    const float* ag = A + (size_t)(m0 + lr) * K + lk;
    const float* bg = B + (size_t)(n0 + lr) * K + lk;

    const int nk = K / BK;

    // ---- prologue: LDG chunk0 -> STS stage0 ; LDG chunk1 -> regs ----
    float4 a0 = *(const float4*)(ag);     float4 a1 = *(const float4*)(ag + 4);
    float4 b0 = *(const float4*)(bg);     float4 b1 = *(const float4*)(bg + 4);
    As[0][lk + 0][lr] = a0.x; As[0][lk + 1][lr] = a0.y;
    As[0][lk + 2][lr] = a0.z; As[0][lk + 3][lr] = a0.w;
    As[0][lk + 4][lr] = a1.x; As[0][lk + 5][lr] = a1.y;
    As[0][lk + 6][lr] = a1.z; As[0][lk + 7][lr] = a1.w;
    Bs[0][lk + 0][lr] = b0.x; Bs[0][lk + 1][lr] = b0.y;
    Bs[0][lk + 2][lr] = b0.z; Bs[0][lk + 3][lr] = b0.w;
    Bs[0][lk + 4][lr] = b1.x; Bs[0][lk + 5][lr] = b1.y;
    Bs[0][lk + 6][lr] = b1.z; Bs[0][lk + 7][lr] = b1.w;
    if (nk > 1) {
        a0 = *(const float4*)(ag + BK);     a1 = *(const float4*)(ag + BK + 4);
        b0 = *(const float4*)(bg + BK);     b1 = *(const float4*)(bg + BK + 4);
    }

    float acc[TM][TN];
#pragma unroll
    for (int i = 0; i < TM; i++)
#pragma unroll
        for (int j = 0; j < TN; j++) acc[i][j] = 0.f;

    for (int c = 0; c < nk; c++) {
        __syncthreads();   // orders STS(c) before compute(c); frees stage (c+1)&1

        // STS chunk c+1 (from register stage, loaded last iteration)
        if (c + 1 < nk) {
            const int s = (c + 1) & 1;
            As[s][lk + 0][lr] = a0.x; As[s][lk + 1][lr] = a0.y;
            As[s][lk + 2][lr] = a0.z; As[s][lk + 3][lr] = a0.w;
            As[s][lk + 4][lr] = a1.x; As[s][lk + 5][lr] = a1.y;
            As[s][lk + 6][lr] = a1.z; As[s][lk + 7][lr] = a1.w;
            Bs[s][lk + 0][lr] = b0.x; Bs[s][lk + 1][lr] = b0.y;
            Bs[s][lk + 2][lr] = b0.z; Bs[s][lk + 3][lr] = b0.w;
            Bs[s][lk + 4][lr] = b1.x; Bs[s][lk + 5][lr] = b1.y;
            Bs[s][lk + 6][lr] = b1.z; Bs[s][lk + 7][lr] = b1.w;
        }
        // LDG chunk c+2 into register stage (hidden under compute below)
        if (c + 2 < nk) {
            const float* a = ag + (size_t)(c + 2) * BK;
            const float* b = bg + (size_t)(c + 2) * BK;
            a0 = *(const float4*)(a);     a1 = *(const float4*)(a + 4);
            b0 = *(const float4*)(b);     b1 = *(const float4*)(b + 4);
        }

        // compute chunk c
        const float (*as)[BM] = As[c & 1];
        const float (*bs)[BN] = Bs[c & 1];
#pragma unroll
        for (int kk = 0; kk < BK; kk++) {
            float4 af0 = *(const float4*)&as[kk][ty * TM];
            float4 af1 = *(const float4*)&as[kk][ty * TM + 4];
            float4 bf0 = *(const float4*)&bs[kk][tx * TN];
            float4 bf1 = *(const float4*)&bs[kk][tx * TN + 4];
            float af[TM] = {af0.x, af0.y, af0.z, af0.w, af1.x, af1.y, af1.z, af1.w};
            float bf[TN] = {bf0.x, bf0.y, bf0.z, bf0.w, bf1.x, bf1.y, bf1.z, bf1.w};
#pragma unroll
            for (int i = 0; i < TM; i++)
#pragma unroll
                for (int j = 0; j < TN; j++)
                    acc[i][j] = fmaf(af[i], bf[j], acc[i][j]);
        }
    }

    // ---- epilogue (identical expressions to round-1 kernel) ----
#pragma unroll
    for (int i = 0; i < TM; i++) {
        const int m = m0 + ty * TM + i;
        float* crow = C + (size_t)m * ldc;
#pragma unroll
        for (int j = 0; j < TN; j++) {
            const int n = n0 + tx * TN + j;
            const float s = acc[i][j];
            if (ACT == 0) {
                crow[n] = s + bias[n];
            } else if (ACT == 1) {
                const float v = s + bias[n];
                crow[n] = (n & 1) ? cosf(v) : sinf(v);
            } else if (ACT == 2) {
                const float v = s + bias[n];
                crow[n] = v;
                crow[N + n] = (n & 1) ? cosf(v) : sinf(v);
            } else { // 3: score
                crow[n] = bias[n] - 2.0f * s;
            }
        }
    }
}

// ---------------- e2[k] = ||emb[k]||^2 ----------------
__global__ void e2_kernel(const float* __restrict__ emb, float* __restrict__ e2)
{
    __shared__ float red[256];
    const int k = blockIdx.x;
    const float* row = emb + (size_t)k * DD;
    float s = 0.f;
    for (int d = threadIdx.x; d < DD; d += 256) { float v = row[d]; s += v * v; }
    red[threadIdx.x] = s;
    __syncthreads();
    for (int o = 128; o > 0; o >>= 1) {
        if (threadIdx.x < o) red[threadIdx.x] += red[threadIdx.x + o];
        __syncthreads();
    }
    if (threadIdx.x == 0) e2[k] = red[0];
}

// ---------------- per-row argmin over K scores (first-index tie-break) -------
__global__ void argmin_kernel(const float* __restrict__ scores, int* __restrict__ idx)
{
    __shared__ float bv[256];
    __shared__ int   bi[256];
    const int n = blockIdx.x;
    const float* row = scores + (size_t)n * KK;
    float best = 3.4e38f;
    int besti = 0;
    for (int k = threadIdx.x; k < KK; k += 256) {
        float v = row[k];
        if (v < best) { best = v; besti = k; }
    }
    bv[threadIdx.x] = best;
    bi[threadIdx.x] = besti;
    __syncthreads();
    for (int o = 128; o > 0; o >>= 1) {
        if (threadIdx.x < o) {
            float vo = bv[threadIdx.x + o];
            int   io = bi[threadIdx.x + o];
            if (vo < bv[threadIdx.x] ||
                (vo == bv[threadIdx.x] && io < bi[threadIdx.x])) {
                bv[threadIdx.x] = vo; bi[threadIdx.x] = io;
            }
        }
        __syncthreads();
    }
    if (threadIdx.x == 0) idx[n] = bi[0];
}

// ---------------- mueller hash (numpy int64 wraparound semantics) ------------
__device__ __forceinline__ long long mueller_hash(long long x)
{
    const unsigned long long C = 73244475ull;
    x = (long long)((unsigned long long)((x >> 16) ^ x) * C);
    x = (long long)((unsigned long long)((x >> 16) ^ x) * C);
    return (x >> 16) ^ x;
}

// ---------------- quantize: out[n] = sum_{i=1..3} emb[hash(idx+i*K)&(K-1)]/3 --
__global__ void quant_kernel(const float* __restrict__ emb,
                             const int* __restrict__ idx,
                             float* __restrict__ out)
{
    const int n = blockIdx.x;
    const long long id = (long long)idx[n];
    int s0 = (int)(mueller_hash(id + 1LL * KK) & (long long)(KK - 1));
    int s1 = (int)(mueller_hash(id + 2LL * KK) & (long long)(KK - 1));
    int s2 = (int)(mueller_hash(id + 3LL * KK) & (long long)(KK - 1));
    const float4* e0 = (const float4*)(emb + (size_t)s0 * DD);
    const float4* e1 = (const float4*)(emb + (size_t)s1 * DD);
    const float4* e2p = (const float4*)(emb + (size_t)s2 * DD);
    float4* o = (float4*)(out + (size_t)n * DD);
    const int d = threadIdx.x;
    float4 a = e0[d], b = e1[d], c = e2p[d];
    float4 r;
    r.x = (a.x / 3.0f + b.x / 3.0f) + c.x / 3.0f;
    r.y = (a.y / 3.0f + b.y / 3.0f) + c.y / 3.0f;
    r.z = (a.z / 3.0f + b.z / 3.0f) + c.z / 3.0f;
    r.w = (a.w / 3.0f + b.w / 3.0f) + c.w / 3.0f;
    o[d] = r;
}

// ---------------- host launcher ----------------
extern "C" void kernel_launch(void* const* d_in, const int* in_sizes, int n_in,
                              void* d_out, int out_size)
{
    const float* x   = (const float*)d_in[0];
    const float* w1  = (const float*)d_in[1];
    const float* b1  = (const float*)d_in[2];
    const float* w2  = (const float*)d_in[3];
    const float* b2  = (const float*)d_in[4];
    const float* w3  = (const float*)d_in[5];
    const float* b3  = (const float*)d_in[6];
    const float* w4  = (const float*)d_in[7];
    const float* b4  = (const float*)d_in[8];
    const float* emb = (const float*)d_in[9];
    float* out = (float*)d_out;

    float *hcat, *h2, *h3, *z, *e2d;
    int* idx;
    cudaGetSymbolAddress((void**)&hcat, g_hcat);
    cudaGetSymbolAddress((void**)&h2,   g_h2);
    cudaGetSymbolAddress((void**)&h3,   g_h3);
    cudaGetSymbolAddress((void**)&z,    g_z);
    cudaGetSymbolAddress((void**)&e2d,  g_e2);
    cudaGetSymbolAddress((void**)&idx,  g_idx);

    e2_kernel<<<KK, 256>>>(emb, e2d);

    // G1: hcat = [h1, fourier(h1)], h1 = x @ w1.T + b1
    gemm_ff<2><<<dim3(HH / BN, NN / BM), 256>>>(x, w1, b1, hcat, NN, HH, DD, 2 * HH);
    // G2: h2 = fourier(hcat @ w2.T + b2)
    gemm_ff<1><<<dim3(HH / BN, NN / BM), 256>>>(hcat, w2, b2, h2, NN, HH, 2 * HH, HH);
    // G3: h3 = fourier(h2 @ w3.T + b3)
    gemm_ff<1><<<dim3(HH / BN, NN / BM), 256>>>(h2, w3, b3, h3, NN, HH, HH, HH);
    // G4: z = h3 @ w4.T + b4
    gemm_ff<0><<<dim3(DD / BN, NN / BM), 256>>>(h3, w4, b4, z, NN, DD, HH, DD);
    // G5: scores = e2[k] - 2 * z @ emb.T  (reuse h2)
    gemm_ff<3><<<dim3(KK / BN, NN / BM), 256>>>(z, emb, e2d, h2, NN, KK, DD, KK);

    argmin_kernel<<<NN, 256>>>(h2, idx);
    quant_kernel<<<NN, 256>>>(emb, idx, out);
}

// round 9
// speedup vs baseline: 1.0886x; 1.0579x over previous
#include <cuda_runtime.h>
#include <cuda_bf16.h>
#include <math.h>
#include <stdint.h>

// Problem dims (fixed by the dataset)
#define NN 8192
#define DD 1024
#define HH 4096
#define KK 4096   // codebook

// ---------------- scratch (static __device__, allocation-free) ----------------
__device__ float g_hcat[(size_t)NN * 2 * HH];   // [8192, 8192]
__device__ float g_h2[(size_t)NN * HH];         // [8192, 4096] (reused for scores)
__device__ float g_h3[(size_t)NN * HH];         // [8192, 4096]
__device__ float g_z[(size_t)NN * DD];          // [8192, 1024]
__device__ float g_e2[KK];
__device__ int   g_idx[NN];

// ============================ FFMA GEMM (fat tile) ============================
// C[m,n] = act( sum_k A[m,k]*B[n,k] + bias[n] ),  A:[M,K], B:[N,K] row-major.
// CTA tile 256x128, 256 threads, thread tile 16x8 (warp 64x64, lanes 4ty x 8tx).
// Per-element: single accumulator, strictly ascending k (fmaf) -> bit-identical
// to the round-1/7 kernels (rel_err 6.29e-8). Register-staged double buffer,
// one barrier per BK=16 chunk.
#define BM 256
#define BN 128
#define BK 16
#define TM 16
#define TN 8

// ACT: 0=bias  1=fourier(bias+acc)  2=cat raw+fourier (ldc=2N)  3=score bias-2*acc
template <int ACT>
__global__ __launch_bounds__(256, 1)
void gemm_ff2(const float* __restrict__ A, const float* __restrict__ B,
              const float* __restrict__ bias, float* __restrict__ C,
              int M, int N, int K, int ldc)
{
    __shared__ float As[2][BK][BM];   // 32 KB
    __shared__ float Bs[2][BK][BN];   // 16 KB

    const int tid  = threadIdx.x;
    const int lane = tid & 31;
    const int wid  = tid >> 5;
    const int ty = lane >> 3;           // 0..3  (row groups of 16)
    const int tx = lane & 7;            // 0..7  (col groups of 8)
    const int wm = (wid >> 1) * 64;     // 4 warp-rows
    const int wn = (wid & 1) * 64;      // 2 warp-cols
    const int m0 = blockIdx.y * BM;
    const int n0 = blockIdx.x * BN;

    // loader mapping: A: thread tid owns full row tid (16 floats)
    //                 B: 2 threads per row, 8 k's each
    const int blr = tid >> 1;
    const int blk = (tid & 1) * 8;
    const float* ag = A + (size_t)(m0 + tid) * K;
    const float* bg = B + (size_t)(n0 + blr) * K + blk;

    const int nk = K / BK;

    // ---- prologue: LDG chunk0 -> STS stage0 ; LDG chunk1 -> regs ----
    float4 a0, a1, a2, a3, b0, b1;
    a0 = *(const float4*)(ag);      a1 = *(const float4*)(ag + 4);
    a2 = *(const float4*)(ag + 8);  a3 = *(const float4*)(ag + 12);
    b0 = *(const float4*)(bg);      b1 = *(const float4*)(bg + 4);
    {
        As[0][ 0][tid] = a0.x; As[0][ 1][tid] = a0.y;
        As[0][ 2][tid] = a0.z; As[0][ 3][tid] = a0.w;
        As[0][ 4][tid] = a1.x; As[0][ 5][tid] = a1.y;
        As[0][ 6][tid] = a1.z; As[0][ 7][tid] = a1.w;
        As[0][ 8][tid] = a2.x; As[0][ 9][tid] = a2.y;
        As[0][10][tid] = a2.z; As[0][11][tid] = a2.w;
        As[0][12][tid] = a3.x; As[0][13][tid] = a3.y;
        As[0][14][tid] = a3.z; As[0][15][tid] = a3.w;
        Bs[0][blk + 0][blr] = b0.x; Bs[0][blk + 1][blr] = b0.y;
        Bs[0][blk + 2][blr] = b0.z; Bs[0][blk + 3][blr] = b0.w;
        Bs[0][blk + 4][blr] = b1.x; Bs[0][blk + 5][blr] = b1.y;
        Bs[0][blk + 6][blr] = b1.z; Bs[0][blk + 7][blr] = b1.w;
    }
    if (nk > 1) {
        a0 = *(const float4*)(ag + BK);      a1 = *(const float4*)(ag + BK + 4);
        a2 = *(const float4*)(ag + BK + 8);  a3 = *(const float4*)(ag + BK + 12);
        b0 = *(const float4*)(bg + BK);      b1 = *(const float4*)(bg + BK + 4);
    }

    float acc[TM][TN];
#pragma unroll
    for (int i = 0; i < TM; i++)
#pragma unroll
        for (int j = 0; j < TN; j++) acc[i][j] = 0.f;

    for (int c = 0; c < nk; c++) {
        __syncthreads();

        // STS chunk c+1 (from register stage)
        if (c + 1 < nk) {
            const int s = (c + 1) & 1;
            As[s][ 0][tid] = a0.x; As[s][ 1][tid] = a0.y;
            As[s][ 2][tid] = a0.z; As[s][ 3][tid] = a0.w;
            As[s][ 4][tid] = a1.x; As[s][ 5][tid] = a1.y;
            As[s][ 6][tid] = a1.z; As[s][ 7][tid] = a1.w;
            As[s][ 8][tid] = a2.x; As[s][ 9][tid] = a2.y;
            As[s][10][tid] = a2.z; As[s][11][tid] = a2.w;
            As[s][12][tid] = a3.x; As[s][13][tid] = a3.y;
            As[s][14][tid] = a3.z; As[s][15][tid] = a3.w;
            Bs[s][blk + 0][blr] = b0.x; Bs[s][blk + 1][blr] = b0.y;
            Bs[s][blk + 2][blr] = b0.z; Bs[s][blk + 3][blr] = b0.w;
            Bs[s][blk + 4][blr] = b1.x; Bs[s][blk + 5][blr] = b1.y;
            Bs[s][blk + 6][blr] = b1.z; Bs[s][blk + 7][blr] = b1.w;
        }
        // LDG chunk c+2 into register stage (hidden under compute)
        if (c + 2 < nk) {
            const float* a = ag + (size_t)(c + 2) * BK;
            const float* b = bg + (size_t)(c + 2) * BK;
            a0 = *(const float4*)(a);      a1 = *(const float4*)(a + 4);
            a2 = *(const float4*)(a + 8);  a3 = *(const float4*)(a + 12);
            b0 = *(const float4*)(b);      b1 = *(const float4*)(b + 4);
        }

        // compute chunk c
        const float (*as)[BM] = As[c & 1];
        const float (*bs)[BN] = Bs[c & 1];
#pragma unroll
        for (int kk = 0; kk < BK; kk++) {
            const float* arow = &as[kk][wm + ty * TM];
            const float* brow = &bs[kk][wn + tx * TN];
            float4 af0 = *(const float4*)(arow);
            float4 af1 = *(const float4*)(arow + 4);
            float4 af2 = *(const float4*)(arow + 8);
            float4 af3 = *(const float4*)(arow + 12);
            float4 bf0 = *(const float4*)(brow);
            float4 bf1 = *(const float4*)(brow + 4);
            float af[TM] = {af0.x, af0.y, af0.z, af0.w, af1.x, af1.y, af1.z, af1.w,
                            af2.x, af2.y, af2.z, af2.w, af3.x, af3.y, af3.z, af3.w};
            float bf[TN] = {bf0.x, bf0.y, bf0.z, bf0.w, bf1.x, bf1.y, bf1.z, bf1.w};
#pragma unroll
            for (int i = 0; i < TM; i++)
#pragma unroll
                for (int j = 0; j < TN; j++)
                    acc[i][j] = fmaf(af[i], bf[j], acc[i][j]);
        }
    }

    // ---- epilogue (identical expressions to round-1/7 kernels) ----
#pragma unroll
    for (int i = 0; i < TM; i++) {
        const int m = m0 + wm + ty * TM + i;
        float* crow = C + (size_t)m * ldc;
#pragma unroll
        for (int j = 0; j < TN; j++) {
            const int n = n0 + wn + tx * TN + j;
            const float s = acc[i][j];
            if (ACT == 0) {
                crow[n] = s + bias[n];
            } else if (ACT == 1) {
                const float v = s + bias[n];
                crow[n] = (n & 1) ? cosf(v) : sinf(v);
            } else if (ACT == 2) {
                const float v = s + bias[n];
                crow[n] = v;
                crow[N + n] = (n & 1) ? cosf(v) : sinf(v);
            } else { // 3: score
                crow[n] = bias[n] - 2.0f * s;
            }
        }
    }
}

// ---------------- e2[k] = ||emb[k]||^2 ----------------
__global__ void e2_kernel(const float* __restrict__ emb, float* __restrict__ e2)
{
    __shared__ float red[256];
    const int k = blockIdx.x;
    const float* row = emb + (size_t)k * DD;
    float s = 0.f;
    for (int d = threadIdx.x; d < DD; d += 256) { float v = row[d]; s += v * v; }
    red[threadIdx.x] = s;
    __syncthreads();
    for (int o = 128; o > 0; o >>= 1) {
        if (threadIdx.x < o) red[threadIdx.x] += red[threadIdx.x + o];
        __syncthreads();
    }
    if (threadIdx.x == 0) e2[k] = red[0];
}

// ---------------- per-row argmin over K scores (first-index tie-break) -------
__global__ void argmin_kernel(const float* __restrict__ scores, int* __restrict__ idx)
{
    __shared__ float bv[256];
    __shared__ int   bi[256];
    const int n = blockIdx.x;
    const float* row = scores + (size_t)n * KK;
    float best = 3.4e38f;
    int besti = 0;
    for (int k = threadIdx.x; k < KK; k += 256) {
        float v = row[k];
        if (v < best) { best = v; besti = k; }
    }
    bv[threadIdx.x] = best;
    bi[threadIdx.x] = besti;
    __syncthreads();
    for (int o = 128; o > 0; o >>= 1) {
        if (threadIdx.x < o) {
            float vo = bv[threadIdx.x + o];
            int   io = bi[threadIdx.x + o];
            if (vo < bv[threadIdx.x] ||
                (vo == bv[threadIdx.x] && io < bi[threadIdx.x])) {
                bv[threadIdx.x] = vo; bi[threadIdx.x] = io;
            }
        }
        __syncthreads();
    }
    if (threadIdx.x == 0) idx[n] = bi[0];
}

// ---------------- mueller hash (numpy int64 wraparound semantics) ------------
__device__ __forceinline__ long long mueller_hash(long long x)
{
    const unsigned long long C = 73244475ull;
    x = (long long)((unsigned long long)((x >> 16) ^ x) * C);
    x = (long long)((unsigned long long)((x >> 16) ^ x) * C);
    return (x >> 16) ^ x;
}

// ---------------- quantize: out[n] = sum_{i=1..3} emb[hash(idx+i*K)&(K-1)]/3 --
__global__ void quant_kernel(const float* __restrict__ emb,
                             const int* __restrict__ idx,
                             float* __restrict__ out)
{
    const int n = blockIdx.x;
    const long long id = (long long)idx[n];
    int s0 = (int)(mueller_hash(id + 1LL * KK) & (long long)(KK - 1));
    int s1 = (int)(mueller_hash(id + 2LL * KK) & (long long)(KK - 1));
    int s2 = (int)(mueller_hash(id + 3LL * KK) & (long long)(KK - 1));
    const float4* e0 = (const float4*)(emb + (size_t)s0 * DD);
    const float4* e1 = (const float4*)(emb + (size_t)s1 * DD);
    const float4* e2p = (const float4*)(emb + (size_t)s2 * DD);
    float4* o = (float4*)(out + (size_t)n * DD);
    const int d = threadIdx.x;
    float4 a = e0[d], b = e1[d], c = e2p[d];
    float4 r;
    r.x = (a.x / 3.0f + b.x / 3.0f) + c.x / 3.0f;
    r.y = (a.y / 3.0f + b.y / 3.0f) + c.y / 3.0f;
    r.z = (a.z / 3.0f + b.z / 3.0f) + c.z / 3.0f;
    r.w = (a.w / 3.0f + b.w / 3.0f) + c.w / 3.0f;
    o[d] = r;
}

// ---------------- host launcher ----------------
extern "C" void kernel_launch(void* const* d_in, const int* in_sizes, int n_in,
                              void* d_out, int out_size)
{
    const float* x   = (const float*)d_in[0];
    const float* w1  = (const float*)d_in[1];
    const float* b1  = (const float*)d_in[2];
    const float* w2  = (const float*)d_in[3];
    const float* b2  = (const float*)d_in[4];
    const float* w3  = (const float*)d_in[5];
    const float* b3  = (const float*)d_in[6];
    const float* w4  = (const float*)d_in[7];
    const float* b4  = (const float*)d_in[8];
    const float* emb = (const float*)d_in[9];
    float* out = (float*)d_out;

    float *hcat, *h2, *h3, *z, *e2d;
    int* idx;
    cudaGetSymbolAddress((void**)&hcat, g_hcat);
    cudaGetSymbolAddress((void**)&h2,   g_h2);
    cudaGetSymbolAddress((void**)&h3,   g_h3);
    cudaGetSymbolAddress((void**)&z,    g_z);
    cudaGetSymbolAddress((void**)&e2d,  g_e2);
    cudaGetSymbolAddress((void**)&idx,  g_idx);

    e2_kernel<<<KK, 256>>>(emb, e2d);

    // G1: hcat = [h1, fourier(h1)], h1 = x @ w1.T + b1
    gemm_ff2<2><<<dim3(HH / BN, NN / BM), 256>>>(x, w1, b1, hcat, NN, HH, DD, 2 * HH);
    // G2: h2 = fourier(hcat @ w2.T + b2)
    gemm_ff2<1><<<dim3(HH / BN, NN / BM), 256>>>(hcat, w2, b2, h2, NN, HH, 2 * HH, HH);
    // G3: h3 = fourier(h2 @ w3.T + b3)
    gemm_ff2<1><<<dim3(HH / BN, NN / BM), 256>>>(h2, w3, b3, h3, NN, HH, HH, HH);
    // G4: z = h3 @ w4.T + b4
    gemm_ff2<0><<<dim3(DD / BN, NN / BM), 256>>>(h3, w4, b4, z, NN, DD, HH, DD);
    // G5: scores = e2[k] - 2 * z @ emb.T  (reuse h2)
    gemm_ff2<3><<<dim3(KK / BN, NN / BM), 256>>>(z, emb, e2d, h2, NN, KK, DD, KK);

    argmin_kernel<<<NN, 256>>>(h2, idx);
    quant_kernel<<<NN, 256>>>(emb, idx, out);
}

// round 10
// speedup vs baseline: 1.1505x; 1.0569x over previous
#include <cuda_runtime.h>
#include <cuda_bf16.h>
#include <math.h>
#include <stdint.h>

// Problem dims (fixed by the dataset)
#define NN 8192
#define DD 1024
#define HH 4096
#define KK 4096   // codebook

// ---------------- scratch (static __device__, allocation-free) ----------------
__device__ float g_hcat[(size_t)NN * 2 * HH];   // [8192, 8192]
__device__ float g_h2[(size_t)NN * HH];         // [8192, 4096] (reused for scores)
__device__ float g_h3[(size_t)NN * HH];         // [8192, 4096]
__device__ float g_z[(size_t)NN * DD];          // [8192, 1024]
__device__ float g_e2[KK];
__device__ int   g_idx[NN];

// ============================ FFMA GEMM (fat tile, spread loader) =============
// C[m,n] = act( sum_k A[m,k]*B[n,k] + bias[n] ),  A:[M,K], B:[N,K] row-major.
// CTA tile 256x128, 256 threads, thread tile 16x8 (warp 64x64, lanes 4ty x 8tx).
// Per-element: single accumulator, strictly ascending k (fmaf) -> bit-identical
// to rounds 1/7/9 (rel_err 6.29e-8). Register-staged double buffer, one barrier
// per BK=16 chunk; the 24 STS + 6 LDG of the staging path are spread across the
// kk iterations (one quad = 4 STS + 1 LDG after kk = 1,3,5,7,9,11) so the LSU
// queue is never burst-saturated and FFMA issue stays hot.
#define BM 256
#define BN 128
#define BK 16
#define TM 16
#define TN 8

// ACT: 0=bias  1=fourier(bias+acc)  2=cat raw+fourier (ldc=2N)  3=score bias-2*acc
template <int ACT>
__global__ __launch_bounds__(256, 1)
void gemm_ff3(const float* __restrict__ A, const float* __restrict__ B,
              const float* __restrict__ bias, float* __restrict__ C,
              int M, int N, int K, int ldc)
{
    __shared__ float As[2][BK][BM];   // 32 KB
    __shared__ float Bs[2][BK][BN];   // 16 KB

    const int tid  = threadIdx.x;
    const int lane = tid & 31;
    const int wid  = tid >> 5;
    const int ty = lane >> 3;           // 0..3  (row groups of 16)
    const int tx = lane & 7;            // 0..7  (col groups of 8)
    const int wm = (wid >> 1) * 64;     // 4 warp-rows
    const int wn = (wid & 1) * 64;      // 2 warp-cols
    const int m0 = blockIdx.y * BM;
    const int n0 = blockIdx.x * BN;

    // loader mapping: A: thread tid owns full row tid (16 floats)
    //                 B: 2 threads per row, 8 k's each
    const int blr = tid >> 1;
    const int blk = (tid & 1) * 8;
    const float* ag = A + (size_t)(m0 + tid) * K;
    const float* bg = B + (size_t)(n0 + blr) * K + blk;

    const int nk = K / BK;

    // ---- prologue: LDG chunk0 -> STS stage0 ; LDG chunk1 -> regs ----
    float4 a0, a1, a2, a3, b0, b1;
    a0 = *(const float4*)(ag);      a1 = *(const float4*)(ag + 4);
    a2 = *(const float4*)(ag + 8);  a3 = *(const float4*)(ag + 12);
    b0 = *(const float4*)(bg);      b1 = *(const float4*)(bg + 4);
    {
        As[0][ 0][tid] = a0.x; As[0][ 1][tid] = a0.y;
        As[0][ 2][tid] = a0.z; As[0][ 3][tid] = a0.w;
        As[0][ 4][tid] = a1.x; As[0][ 5][tid] = a1.y;
        As[0][ 6][tid] = a1.z; As[0][ 7][tid] = a1.w;
        As[0][ 8][tid] = a2.x; As[0][ 9][tid] = a2.y;
        As[0][10][tid] = a2.z; As[0][11][tid] = a2.w;
        As[0][12][tid] = a3.x; As[0][13][tid] = a3.y;
        As[0][14][tid] = a3.z; As[0][15][tid] = a3.w;
        Bs[0][blk + 0][blr] = b0.x; Bs[0][blk + 1][blr] = b0.y;
        Bs[0][blk + 2][blr] = b0.z; Bs[0][blk + 3][blr] = b0.w;
        Bs[0][blk + 4][blr] = b1.x; Bs[0][blk + 5][blr] = b1.y;
        Bs[0][blk + 6][blr] = b1.z; Bs[0][blk + 7][blr] = b1.w;
    }
    if (nk > 1) {
        a0 = *(const float4*)(ag + BK);      a1 = *(const float4*)(ag + BK + 4);
        a2 = *(const float4*)(ag + BK + 8);  a3 = *(const float4*)(ag + BK + 12);
        b0 = *(const float4*)(bg + BK);      b1 = *(const float4*)(bg + BK + 4);
    }

    float acc[TM][TN];
#pragma unroll
    for (int i = 0; i < TM; i++)
#pragma unroll
        for (int j = 0; j < TN; j++) acc[i][j] = 0.f;

    for (int c = 0; c < nk; c++) {
        __syncthreads();   // STS(c) visible; stage (c+1)&1 free for writing

        const int s = (c + 1) & 1;                 // stage being filled
        const bool do_sts = (c + 1 < nk);
        const bool do_ldg = (c + 2 < nk);
        const float* an = ag + (size_t)(c + 2) * BK;   // LDG source (chunk c+2)
        const float* bn = bg + (size_t)(c + 2) * BK;

        const float (*as)[BM] = As[c & 1];
        const float (*bs)[BN] = Bs[c & 1];

#pragma unroll
        for (int kk = 0; kk < BK; kk++) {
            // ---- compute kk ----
            const float* arow = &as[kk][wm + ty * TM];
            const float* brow = &bs[kk][wn + tx * TN];
            float4 af0 = *(const float4*)(arow);
            float4 af1 = *(const float4*)(arow + 4);
            float4 af2 = *(const float4*)(arow + 8);
            float4 af3 = *(const float4*)(arow + 12);
            float4 bf0 = *(const float4*)(brow);
            float4 bf1 = *(const float4*)(brow + 4);
            float af[TM] = {af0.x, af0.y, af0.z, af0.w, af1.x, af1.y, af1.z, af1.w,
                            af2.x, af2.y, af2.z, af2.w, af3.x, af3.y, af3.z, af3.w};
            float bf[TN] = {bf0.x, bf0.y, bf0.z, bf0.w, bf1.x, bf1.y, bf1.z, bf1.w};
#pragma unroll
            for (int i = 0; i < TM; i++)
#pragma unroll
                for (int j = 0; j < TN; j++)
                    acc[i][j] = fmaf(af[i], bf[j], acc[i][j]);

            // ---- interleaved staging: retire one quad (STS then reload) ----
            if (kk == 1) {
                if (do_sts) {
                    As[s][0][tid] = a0.x; As[s][1][tid] = a0.y;
                    As[s][2][tid] = a0.z; As[s][3][tid] = a0.w;
                }
                if (do_ldg) a0 = *(const float4*)(an);
            } else if (kk == 3) {
                if (do_sts) {
                    As[s][4][tid] = a1.x; As[s][5][tid] = a1.y;
                    As[s][6][tid] = a1.z; As[s][7][tid] = a1.w;
                }
                if (do_ldg) a1 = *(const float4*)(an + 4);
            } else if (kk == 5) {
                if (do_sts) {
                    As[s][ 8][tid] = a2.x; As[s][ 9][tid] = a2.y;
                    As[s][10][tid] = a2.z; As[s][11][tid] = a2.w;
                }
                if (do_ldg) a2 = *(const float4*)(an + 8);
            } else if (kk == 7) {
                if (do_sts) {
                    As[s][12][tid] = a3.x; As[s][13][tid] = a3.y;
                    As[s][14][tid] = a3.z; As[s][15][tid] = a3.w;
                }
                if (do_ldg) a3 = *(const float4*)(an + 12);
            } else if (kk == 9) {
                if (do_sts) {
                    Bs[s][blk + 0][blr] = b0.x; Bs[s][blk + 1][blr] = b0.y;
                    Bs[s][blk + 2][blr] = b0.z; Bs[s][blk + 3][blr] = b0.w;
                }
                if (do_ldg) b0 = *(const float4*)(bn);
            } else if (kk == 11) {
                if (do_sts) {
                    Bs[s][blk + 4][blr] = b1.x; Bs[s][blk + 5][blr] = b1.y;
                    Bs[s][blk + 6][blr] = b1.z; Bs[s][blk + 7][blr] = b1.w;
                }
                if (do_ldg) b1 = *(const float4*)(bn + 4);
            }
        }
    }

    // ---- epilogue (identical expressions to rounds 1/7/9) ----
#pragma unroll
    for (int i = 0; i < TM; i++) {
        const int m = m0 + wm + ty * TM + i;
        float* crow = C + (size_t)m * ldc;
#pragma unroll
        for (int j = 0; j < TN; j++) {
            const int n = n0 + wn + tx * TN + j;
            const float s = acc[i][j];
            if (ACT == 0) {
                crow[n] = s + bias[n];
            } else if (ACT == 1) {
                const float v = s + bias[n];
                crow[n] = (n & 1) ? cosf(v) : sinf(v);
            } else if (ACT == 2) {
                const float v = s + bias[n];
                crow[n] = v;
                crow[N + n] = (n & 1) ? cosf(v) : sinf(v);
            } else { // 3: score
                crow[n] = bias[n] - 2.0f * s;
            }
        }
    }
}

// ---------------- e2[k] = ||emb[k]||^2 ----------------
__global__ void e2_kernel(const float* __restrict__ emb, float* __restrict__ e2)
{
    __shared__ float red[256];
    const int k = blockIdx.x;
    const float* row = emb + (size_t)k * DD;
    float s = 0.f;
    for (int d = threadIdx.x; d < DD; d += 256) { float v = row[d]; s += v * v; }
    red[threadIdx.x] = s;
    __syncthreads();
    for (int o = 128; o > 0; o >>= 1) {
        if (threadIdx.x < o) red[threadIdx.x] += red[threadIdx.x + o];
        __syncthreads();
    }
    if (threadIdx.x == 0) e2[k] = red[0];
}

// ---------------- per-row argmin over K scores (first-index tie-break) -------
__global__ void argmin_kernel(const float* __restrict__ scores, int* __restrict__ idx)
{
    __shared__ float bv[256];
    __shared__ int   bi[256];
    const int n = blockIdx.x;
    const float* row = scores + (size_t)n * KK;
    float best = 3.4e38f;
    int besti = 0;
    for (int k = threadIdx.x; k < KK; k += 256) {
        float v = row[k];
        if (v < best) { best = v; besti = k; }
    }
    bv[threadIdx.x] = best;
    bi[threadIdx.x] = besti;
    __syncthreads();
    for (int o = 128; o > 0; o >>= 1) {
        if (threadIdx.x < o) {
            float vo = bv[threadIdx.x + o];
            int   io = bi[threadIdx.x + o];
            if (vo < bv[threadIdx.x] ||
                (vo == bv[threadIdx.x] && io < bi[threadIdx.x])) {
                bv[threadIdx.x] = vo; bi[threadIdx.x] = io;
            }
        }
        __syncthreads();
    }
    if (threadIdx.x == 0) idx[n] = bi[0];
}

// ---------------- mueller hash (numpy int64 wraparound semantics) ------------
__device__ __forceinline__ long long mueller_hash(long long x)
{
    const unsigned long long C = 73244475ull;
    x = (long long)((unsigned long long)((x >> 16) ^ x) * C);
    x = (long long)((unsigned long long)((x >> 16) ^ x) * C);
    return (x >> 16) ^ x;
}

// ---------------- quantize: out[n] = sum_{i=1..3} emb[hash(idx+i*K)&(K-1)]/3 --
__global__ void quant_kernel(const float* __restrict__ emb,
                             const int* __restrict__ idx,
                             float* __restrict__ out)
{
    const int n = blockIdx.x;
    const long long id = (long long)idx[n];
    int s0 = (int)(mueller_hash(id + 1LL * KK) & (long long)(KK - 1));
    int s1 = (int)(mueller_hash(id + 2LL * KK) & (long long)(KK - 1));
    int s2 = (int)(mueller_hash(id + 3LL * KK) & (long long)(KK - 1));
    const float4* e0 = (const float4*)(emb + (size_t)s0 * DD);
    const float4* e1 = (const float4*)(emb + (size_t)s1 * DD);
    const float4* e2p = (const float4*)(emb + (size_t)s2 * DD);
    float4* o = (float4*)(out + (size_t)n * DD);
    const int d = threadIdx.x;
    float4 a = e0[d], b = e1[d], c = e2p[d];
    float4 r;
    r.x = (a.x / 3.0f + b.x / 3.0f) + c.x / 3.0f;
    r.y = (a.y / 3.0f + b.y / 3.0f) + c.y / 3.0f;
    r.z = (a.z / 3.0f + b.z / 3.0f) + c.z / 3.0f;
    r.w = (a.w / 3.0f + b.w / 3.0f) + c.w / 3.0f;
    o[d] = r;
}

// ---------------- host launcher ----------------
extern "C" void kernel_launch(void* const* d_in, const int* in_sizes, int n_in,
                              void* d_out, int out_size)
{
    const float* x   = (const float*)d_in[0];
    const float* w1  = (const float*)d_in[1];
    const float* b1  = (const float*)d_in[2];
    const float* w2  = (const float*)d_in[3];
    const float* b2  = (const float*)d_in[4];
    const float* w3  = (const float*)d_in[5];
    const float* b3  = (const float*)d_in[6];
    const float* w4  = (const float*)d_in[7];
    const float* b4  = (const float*)d_in[8];
    const float* emb = (const float*)d_in[9];
    float* out = (float*)d_out;

    float *hcat, *h2, *h3, *z, *e2d;
    int* idx;
    cudaGetSymbolAddress((void**)&hcat, g_hcat);
    cudaGetSymbolAddress((void**)&h2,   g_h2);
    cudaGetSymbolAddress((void**)&h3,   g_h3);
    cudaGetSymbolAddress((void**)&z,    g_z);
    cudaGetSymbolAddress((void**)&e2d,  g_e2);
    cudaGetSymbolAddress((void**)&idx,  g_idx);

    e2_kernel<<<KK, 256>>>(emb, e2d);

    // G1: hcat = [h1, fourier(h1)], h1 = x @ w1.T + b1
    gemm_ff3<2><<<dim3(HH / BN, NN / BM), 256>>>(x, w1, b1, hcat, NN, HH, DD, 2 * HH);
    // G2: h2 = fourier(hcat @ w2.T + b2)
    gemm_ff3<1><<<dim3(HH / BN, NN / BM), 256>>>(hcat, w2, b2, h2, NN, HH, 2 * HH, HH);
    // G3: h3 = fourier(h2 @ w3.T + b3)
    gemm_ff3<1><<<dim3(HH / BN, NN / BM), 256>>>(h2, w3, b3, h3, NN, HH, HH, HH);
    // G4: z = h3 @ w4.T + b4
    gemm_ff3<0><<<dim3(DD / BN, NN / BM), 256>>>(h3, w4, b4, z, NN, DD, HH, DD);
    // G5: scores = e2[k] - 2 * z @ emb.T  (reuse h2)
    gemm_ff3<3><<<dim3(KK / BN, NN / BM), 256>>>(z, emb, e2d, h2, NN, KK, DD, KK);

    argmin_kernel<<<NN, 256>>>(h2, idx);
    quant_kernel<<<NN, 256>>>(emb, idx, out);
}